// round 1
// baseline (speedup 1.0000x reference)
#include <cuda_runtime.h>
#include <cstdint>

#define NN 150000
#define NE 2400000

// Scratch (static __device__ — no allocations allowed)
__device__ float4 g_buf1[NN * 8];   // xw / hw   (19.2 MB)
__device__ float4 g_buf2[NN * 8];   // agg / agg2 (19.2 MB)
__device__ float  g_dinv[NN];       // deg -> dinv

// ---------------------------------------------------------------------------
// 1) degree init: deg = 1 (self loop)
__global__ void k_deg_init(int n) {
    int i = blockIdx.x * blockDim.x + threadIdx.x;
    if (i < n) g_dinv[i] = 1.0f;
}

// 2) degree accumulate over dst
__global__ void k_deg_edges(const int* __restrict__ dst, int ne) {
    int e = blockIdx.x * blockDim.x + threadIdx.x;
    if (e < ne) atomicAdd(&g_dinv[dst[e]], 1.0f);
}

// 3) conv1 node: dinv = rsqrt(deg); xw = x @ W1; buf1 = xw; buf2 = xw*dinv^2
__global__ void k_conv1(const float* __restrict__ x, const float* __restrict__ W1, int n) {
    __shared__ float Ws[6 * 32];
    for (int t = threadIdx.x; t < 192; t += blockDim.x) Ws[t] = W1[t];
    __syncthreads();
    int i = blockIdx.x * blockDim.x + threadIdx.x;
    if (i >= n) return;

    float dinv = rsqrtf(g_dinv[i]);
    g_dinv[i] = dinv;
    float d2 = dinv * dinv;

    float xi[6];
#pragma unroll
    for (int k = 0; k < 6; k++) xi[k] = x[i * 6 + k];

    float acc[32];
#pragma unroll
    for (int j = 0; j < 32; j++) {
        float s = 0.f;
#pragma unroll
        for (int k = 0; k < 6; k++) s += xi[k] * Ws[k * 32 + j];
        acc[j] = s;
    }
#pragma unroll
    for (int q = 0; q < 8; q++) {
        float4 v = make_float4(acc[4*q], acc[4*q+1], acc[4*q+2], acc[4*q+3]);
        g_buf1[i * 8 + q] = v;
        g_buf2[i * 8 + q] = make_float4(v.x * d2, v.y * d2, v.z * d2, v.w * d2);
    }
}

// 4) edge scatter: 8 threads per edge, each handles one float4 component group.
//    agg[dst] += buf1[src] * dinv[src]*dinv[dst]  via red.global.add.v4.f32
__global__ void k_edge_scatter(const int* __restrict__ src, const int* __restrict__ dst,
                               long ne) {
    long tid = (long)blockIdx.x * blockDim.x + threadIdx.x;
    long e = tid >> 3;
    int  c = (int)(tid & 7);
    if (e >= ne) return;
    int s = src[e];
    int d = dst[e];
    float nrm = g_dinv[s] * g_dinv[d];
    float4 v = g_buf1[(long)s * 8 + c];
    float4* p = &g_buf2[(long)d * 8 + c];
    asm volatile("red.global.add.v4.f32 [%0], {%1, %2, %3, %4};"
                 :: "l"(p), "f"(v.x * nrm), "f"(v.y * nrm), "f"(v.z * nrm), "f"(v.w * nrm)
                 : "memory");
}

// 5) conv2 node: h = relu(buf2 + b1); hw = h @ W2; buf1 = hw; buf2 = hw*dinv^2
__global__ void k_conv2(const float* __restrict__ b1, const float* __restrict__ W2, int n) {
    __shared__ float Ws[32 * 32];
    __shared__ float bs[32];
    for (int t = threadIdx.x; t < 1024; t += blockDim.x) Ws[t] = W2[t];
    if (threadIdx.x < 32) bs[threadIdx.x] = b1[threadIdx.x];
    __syncthreads();
    int i = blockIdx.x * blockDim.x + threadIdx.x;
    if (i >= n) return;

    float h[32];
#pragma unroll
    for (int q = 0; q < 8; q++) {
        float4 v = g_buf2[i * 8 + q];
        h[4*q+0] = fmaxf(v.x + bs[4*q+0], 0.f);
        h[4*q+1] = fmaxf(v.y + bs[4*q+1], 0.f);
        h[4*q+2] = fmaxf(v.z + bs[4*q+2], 0.f);
        h[4*q+3] = fmaxf(v.w + bs[4*q+3], 0.f);
    }
    float acc[32];
#pragma unroll
    for (int j = 0; j < 32; j++) acc[j] = 0.f;
#pragma unroll
    for (int k = 0; k < 32; k++) {
        float hk = h[k];
#pragma unroll
        for (int j = 0; j < 32; j++) acc[j] += hk * Ws[k * 32 + j];
    }
    float dinv = g_dinv[i];
    float d2 = dinv * dinv;
#pragma unroll
    for (int q = 0; q < 8; q++) {
        float4 v = make_float4(acc[4*q], acc[4*q+1], acc[4*q+2], acc[4*q+3]);
        g_buf1[i * 8 + q] = v;
        g_buf2[i * 8 + q] = make_float4(v.x * d2, v.y * d2, v.z * d2, v.w * d2);
    }
}

// 6) heads: features = buf2 + b2 -> out; two small MLPs -> topo / normals / uvs
__global__ void k_heads(const float* __restrict__ b2,
                        const float* __restrict__ Wt1, const float* __restrict__ bt1,
                        const float* __restrict__ Wt2, const float* __restrict__ bt2,
                        const float* __restrict__ Wa1, const float* __restrict__ ba1,
                        const float* __restrict__ Wa2, const float* __restrict__ ba2,
                        float* __restrict__ out, int n) {
    __shared__ float s_b2[32];
    __shared__ float s_Wt1[32 * 16];
    __shared__ float s_bt1[16];
    __shared__ float s_Wt2[16];
    __shared__ float s_Wa1[32 * 16];
    __shared__ float s_ba1[16];
    __shared__ float s_Wa2[16 * 6];
    __shared__ float s_ba2[6];
    __shared__ float s_bt2;
    for (int t = threadIdx.x; t < 512; t += blockDim.x) { s_Wt1[t] = Wt1[t]; s_Wa1[t] = Wa1[t]; }
    for (int t = threadIdx.x; t < 96;  t += blockDim.x) s_Wa2[t] = Wa2[t];
    if (threadIdx.x < 32) s_b2[threadIdx.x] = b2[threadIdx.x];
    if (threadIdx.x < 16) { s_bt1[threadIdx.x] = bt1[threadIdx.x];
                            s_Wt2[threadIdx.x] = Wt2[threadIdx.x];
                            s_ba1[threadIdx.x] = ba1[threadIdx.x]; }
    if (threadIdx.x < 6)  s_ba2[threadIdx.x] = ba2[threadIdx.x];
    if (threadIdx.x == 0) s_bt2 = bt2[0];
    __syncthreads();

    int i = blockIdx.x * blockDim.x + threadIdx.x;
    if (i >= n) return;

    float f[32];
#pragma unroll
    for (int q = 0; q < 8; q++) {
        float4 v = g_buf2[i * 8 + q];
        f[4*q+0] = v.x + s_b2[4*q+0];
        f[4*q+1] = v.y + s_b2[4*q+1];
        f[4*q+2] = v.z + s_b2[4*q+2];
        f[4*q+3] = v.w + s_b2[4*q+3];
    }

    // features output at offset 7*n (after topo[n], normals[3n], uvs[3n])
    float4* fout = (float4*)(out + (long)7 * n + (long)i * 32);
#pragma unroll
    for (int q = 0; q < 8; q++)
        fout[q] = make_float4(f[4*q], f[4*q+1], f[4*q+2], f[4*q+3]);

    // topology head: 32 -> 16 relu -> 1
    float t1[16];
#pragma unroll
    for (int j = 0; j < 16; j++) {
        float s = s_bt1[j];
#pragma unroll
        for (int k = 0; k < 32; k++) s += f[k] * s_Wt1[k * 16 + j];
        t1[j] = fmaxf(s, 0.f);
    }
    float topo = s_bt2;
#pragma unroll
    for (int j = 0; j < 16; j++) topo += t1[j] * s_Wt2[j];
    out[i] = topo;

    // attribute head: 32 -> 16 relu -> 6
    float a1[16];
#pragma unroll
    for (int j = 0; j < 16; j++) {
        float s = s_ba1[j];
#pragma unroll
        for (int k = 0; k < 32; k++) s += f[k] * s_Wa1[k * 16 + j];
        a1[j] = fmaxf(s, 0.f);
    }
    float attr[6];
#pragma unroll
    for (int m = 0; m < 6; m++) {
        float s = s_ba2[m];
#pragma unroll
        for (int j = 0; j < 16; j++) s += a1[j] * s_Wa2[j * 6 + m];
        attr[m] = s;
    }
    long nb = n;
    out[nb     + (long)i * 3 + 0] = attr[0];
    out[nb     + (long)i * 3 + 1] = attr[1];
    out[nb     + (long)i * 3 + 2] = attr[2];
    out[nb * 4 + (long)i * 3 + 0] = attr[3];
    out[nb * 4 + (long)i * 3 + 1] = attr[4];
    out[nb * 4 + (long)i * 3 + 2] = attr[5];
}

// ---------------------------------------------------------------------------
extern "C" void kernel_launch(void* const* d_in, const int* in_sizes, int n_in,
                              void* d_out, int out_size) {
    const float* x   = (const float*)d_in[0];
    const int*   ei  = (const int*)d_in[1];
    const float* W1  = (const float*)d_in[2];
    const float* b1  = (const float*)d_in[3];
    const float* W2  = (const float*)d_in[4];
    const float* b2  = (const float*)d_in[5];
    const float* Wt1 = (const float*)d_in[6];
    const float* bt1 = (const float*)d_in[7];
    const float* Wt2 = (const float*)d_in[8];
    const float* bt2 = (const float*)d_in[9];
    const float* Wa1 = (const float*)d_in[10];
    const float* ba1 = (const float*)d_in[11];
    const float* Wa2 = (const float*)d_in[12];
    const float* ba2 = (const float*)d_in[13];
    float* out = (float*)d_out;

    int n  = in_sizes[0] / 6;       // nodes
    int ne = in_sizes[1] / 2;       // edges
    const int* src = ei;
    const int* dst = ei + ne;

    const int B = 256;
    int gn = (n + B - 1) / B;
    int ge = (ne + B - 1) / B;
    long scat_threads = (long)ne * 8;
    int gs = (int)((scat_threads + B - 1) / B);

    k_deg_init<<<gn, B>>>(n);
    k_deg_edges<<<ge, B>>>(dst, ne);
    k_conv1<<<gn, B>>>(x, W1, n);
    k_edge_scatter<<<gs, B>>>(src, dst, ne);
    k_conv2<<<gn, B>>>(b1, W2, n);
    k_edge_scatter<<<gs, B>>>(src, dst, ne);
    k_heads<<<gn, B>>>(b2, Wt1, bt1, Wt2, bt2, Wa1, ba1, Wa2, ba2, out, n);
}